// round 8
// baseline (speedup 1.0000x reference)
#include <cuda_runtime.h>
#include <math.h>

#define NS 4096
#define SL 168
#define HZ 24
#define TT 192          // SL + HZ
#define GE 192          // effective gate columns (i,g,o quadrants; f-gate dead)
#define SA_STRIDE 68    // padded smem stride (xg_kernel only)
#define P1_BUF 12       // phase1 warp-private buffer stride (floats, 48B)
#define NWT (NS * SL / 8)   // 86016 warp tiles of 8 rows

typedef unsigned long long ull;

// ---------------- device scratch (allocation-free rule: __device__ globals) --
__device__ __align__(16) float g_W0T[32 * GE];          // layer0 x-part, [k][col]
__device__ __align__(16) float g_W1T[64 * GE];          // layer1, [k][col]
__device__ __align__(16) float g_Wy[GE];                // rank-1 y weights
__device__ __align__(16) float g_C0[GE];                // fused layer0 bias
__device__ __align__(16) float g_C1[GE];                // fused layer1 bias
__device__ __align__(16) float g_XGf[(size_t)NS * HZ * GE];  // Xf @ W0x^T + C0
__device__ float g_carry[NS];

// ---------------- packed f32x2 helpers (sm_103a FFMA2 path) ------------------
__device__ __forceinline__ ull splat2(float x) {
    ull r;
    asm("mov.b64 %0, {%1, %1};" : "=l"(r) : "r"(__float_as_uint(x)));
    return r;
}
__device__ __forceinline__ void ffma2(ull& d, ull a, ull b) {
    asm("fma.rn.f32x2 %0, %1, %2, %3;" : "=l"(d) : "l"(a), "l"(b), "l"(d));
}
__device__ __forceinline__ void unpack2(float& lo, float& hi, ull v) {
    unsigned int l, h;
    asm("mov.b64 {%0, %1}, %2;" : "=r"(l), "=r"(h) : "l"(v));
    lo = __uint_as_float(l);
    hi = __uint_as_float(h);
}

// ---------------- math helpers ----------------------------------------------
__device__ __forceinline__ float sigf(float x) {
    return 1.0f / (1.0f + __expf(-x));
}
__device__ __forceinline__ float tanh_fast(float x) {
    float e = __expf(2.0f * x);
    return (e - 1.0f) / (e + 1.0f);
}
__device__ __forceinline__ float lstm_h(float gi, float gg, float go) {
    float c = sigf(gi) * tanh_fast(gg);
    return sigf(go) * tanh_fast(c);
}
__device__ __forceinline__ float softplus_f(float z) {
    return (z > 15.0f) ? z : log1pf(__expf(z));
}

// ---------------- setup: transposed/pruned weights + fused constants --------
__global__ void setup_kernel(const float* __restrict__ W_embed,
                             const float* __restrict__ b_embed,
                             const float* __restrict__ W_ih,
                             const float* __restrict__ b_ih,
                             const float* __restrict__ b_hh) {
    int col = threadIdx.x;
    if (col >= GE) return;
    int q = col >> 6, j = col & 63;
    int grow = (q == 0) ? j : ((q == 1) ? (128 + j) : (192 + j));  // i / g / o
    const float* w0 = W_ih + grow * 64;
    const float* w1 = W_ih + 256 * 64 + grow * 64;
    for (int k = 0; k < 32; k++) g_W0T[k * GE + col] = w0[k];
    for (int k = 0; k < 64; k++) g_W1T[k * GE + col] = w1[k];
    float wy = 0.0f, cb = 0.0f;
    for (int e = 0; e < 32; e++) {
        wy = fmaf(w0[32 + e], W_embed[e], wy);
        cb = fmaf(w0[32 + e], b_embed[e], cb);
    }
    g_Wy[col] = wy;
    g_C0[col] = b_ih[grow] + b_hh[grow] + cb;
    g_C1[col] = b_ih[256 + grow] + b_hh[256 + grow];
}

// ------------- 64-row block-tile GEMM (xg_kernel only) ----------------------
template <int K>
__device__ __forceinline__ void gemm_tile(const float* __restrict__ sA,
                                          const float* __restrict__ sB,
                                          int m0, int c0i, float acc[8][3][2]) {
    ull accp[4][3][2];
#pragma unroll
    for (int p = 0; p < 4; p++)
#pragma unroll
        for (int q = 0; q < 3; q++) { accp[p][q][0] = 0ULL; accp[p][q][1] = 0ULL; }
#pragma unroll 4
    for (int k = 0; k < K; k++) {
        ull ap[4];
        const ull* pa = (const ull*)&sA[k * SA_STRIDE + m0];
#pragma unroll
        for (int p = 0; p < 4; p++) ap[p] = pa[p];
        ull bs[3][2];
#pragma unroll
        for (int q = 0; q < 3; q++) {
            float2 t = *(const float2*)&sB[k * GE + q * 64 + c0i];
            bs[q][0] = splat2(t.x);
            bs[q][1] = splat2(t.y);
        }
#pragma unroll
        for (int p = 0; p < 4; p++)
#pragma unroll
            for (int q = 0; q < 3; q++) {
                ffma2(accp[p][q][0], ap[p], bs[q][0]);
                ffma2(accp[p][q][1], ap[p], bs[q][1]);
            }
    }
#pragma unroll
    for (int p = 0; p < 4; p++)
#pragma unroll
        for (int q = 0; q < 3; q++)
#pragma unroll
            for (int j = 0; j < 2; j++)
                unpack2(acc[2 * p][q][j], acc[2 * p + 1][q][j], accp[p][q][j]);
}

// ------------- warp-private 8-row GEMM (phase1): A broadcast at m0=0 --------
template <int K>
__device__ __forceinline__ void gemm8(const float* __restrict__ sA,
                                      const float* __restrict__ sB,
                                      int c0i, float acc[8][3][2]) {
    ull accp[4][3][2];
#pragma unroll
    for (int p = 0; p < 4; p++)
#pragma unroll
        for (int q = 0; q < 3; q++) { accp[p][q][0] = 0ULL; accp[p][q][1] = 0ULL; }
#pragma unroll 4
    for (int k = 0; k < K; k++) {
        ull ap[4];
        const ull* pa = (const ull*)(sA + k * P1_BUF);
#pragma unroll
        for (int p = 0; p < 4; p++) ap[p] = pa[p];   // warp-uniform broadcast
        ull bs[3][2];
#pragma unroll
        for (int q = 0; q < 3; q++) {
            float2 t = *(const float2*)&sB[k * GE + q * 64 + c0i];
            bs[q][0] = splat2(t.x);
            bs[q][1] = splat2(t.y);
        }
#pragma unroll
        for (int p = 0; p < 4; p++)
#pragma unroll
            for (int q = 0; q < 3; q++) {
                ffma2(accp[p][q][0], ap[p], bs[q][0]);
                ffma2(accp[p][q][1], ap[p], bs[q][1]);
            }
    }
#pragma unroll
    for (int p = 0; p < 4; p++)
#pragma unroll
        for (int q = 0; q < 3; q++)
#pragma unroll
            for (int j = 0; j < 2; j++)
                unpack2(acc[2 * p][q][j], acc[2 * p + 1][q][j], accp[p][q][j]);
}

// ---------------- Xf pre-GEMM: XGf = Xf @ W0x^T + C0 ------------------------
__global__ __launch_bounds__(256) void xg_kernel(const float* __restrict__ Xf) {
    __shared__ float sW0[32 * GE];
    __shared__ float sA[32 * SA_STRIDE];
    int tid = threadIdx.x, tn = tid & 31, tm = tid >> 5;
    {
        float4* d = (float4*)sW0;
        const float4* s = (const float4*)g_W0T;
        for (int i = tid; i < 32 * GE / 4; i += 256) d[i] = s[i];
    }
    int r0 = blockIdx.x * 64;
    const float4* src = (const float4*)Xf + (size_t)r0 * 8;
    for (int v = tid; v < 512; v += 256) {
        int m = v >> 3, kq = v & 7;
        float4 d = src[m * 8 + kq];
        int kb = kq * 4;
        sA[(kb + 0) * SA_STRIDE + m] = d.x;
        sA[(kb + 1) * SA_STRIDE + m] = d.y;
        sA[(kb + 2) * SA_STRIDE + m] = d.z;
        sA[(kb + 3) * SA_STRIDE + m] = d.w;
    }
    __syncthreads();
    int m0 = tm * 8, c0i = 2 * tn;
    float acc[8][3][2];
    gemm_tile<32>(sA, sW0, m0, c0i, acc);
    float cc[3][2];
#pragma unroll
    for (int q = 0; q < 3; q++) {
        cc[q][0] = g_C0[q * 64 + c0i];
        cc[q][1] = g_C0[q * 64 + c0i + 1];
    }
#pragma unroll
    for (int i = 0; i < 8; i++) {
        size_t base = (size_t)(r0 + m0 + i) * GE;
#pragma unroll
        for (int q = 0; q < 3; q++) {
            float2 o;
            o.x = acc[i][q][0] + cc[q][0];
            o.y = acc[i][q][1] + cc[q][1];
            *(float2*)&g_XGf[base + q * 64 + c0i] = o;
        }
    }
}

// ---------------- reductions -------------------------------------------------
__device__ __forceinline__ void reduce_mu_sig8(float pmu[8], float psg[8]) {
#pragma unroll
    for (int off = 16; off; off >>= 1) {
#pragma unroll
        for (int i = 0; i < 8; i++) {
            pmu[i] += __shfl_xor_sync(0xffffffffu, pmu[i], off);
            psg[i] += __shfl_xor_sync(0xffffffffu, psg[i], off);
        }
    }
}
__device__ __forceinline__ void reduce_mu_sig2(float pmu[2], float psg[2]) {
#pragma unroll
    for (int off = 16; off; off >>= 1) {
#pragma unroll
        for (int i = 0; i < 2; i++) {
            pmu[i] += __shfl_xor_sync(0xffffffffu, pmu[i], off);
            psg[i] += __shfl_xor_sync(0xffffffffu, psg[i], off);
        }
    }
}

// ---------------- phase 1: teacher-forced steps, warp-private tiles ----------
// Each warp owns 8 rows x all 192 cols. Its staging buffer is warp-private, and
// its 32 threads produce exactly the 64 h-columns it needs for layer1, so the
// whole mainloop runs with __syncwarp only (weights are block-shared, RO).
#define SM1_FLOATS (32 * GE + 64 * GE + 8 * 64 * P1_BUF + 64 + 3 * GE)
#define SM1_BYTES (SM1_FLOATS * 4)

__global__ __launch_bounds__(256, 2) void phase1_kernel(
    const float* __restrict__ X, const float* __restrict__ Y,
    const float* __restrict__ W_mu, const float* __restrict__ b_mu,
    const float* __restrict__ W_sigma, const float* __restrict__ b_sigma,
    float* __restrict__ out_ypred, float* __restrict__ out_mu,
    float* __restrict__ out_sig) {
    extern __shared__ float sm[];
    float* sW0  = sm;                        // 6144
    float* sW1  = sW0 + 32 * GE;             // 12288
    float* sBuf = sW1 + 64 * GE;             // 8 * 768
    float* sY   = sBuf + 8 * 64 * P1_BUF;    // 64
    float* swy  = sY + 64;                   // 192
    float* sc0  = swy + GE;                  // 192
    float* sc1  = sc0 + GE;                  // 192

    int tid = threadIdx.x, tn = tid & 31, wid = tid >> 5;
    {
        float4* d = (float4*)sW0; const float4* s = (const float4*)g_W0T;
        for (int i = tid; i < 1536; i += 256) d[i] = s[i];
    }
    {
        float4* d = (float4*)sW1; const float4* s = (const float4*)g_W1T;
        for (int i = tid; i < 3072; i += 256) d[i] = s[i];
    }
    if (tid < GE) { swy[tid] = g_Wy[tid]; sc0[tid] = g_C0[tid]; sc1[tid] = g_C1[tid]; }
    __syncthreads();

    float* buf = sBuf + wid * 64 * P1_BUF;
    float* syw = sY + wid * 8;
    int c0i = 2 * tn;
    float swy_r[3][2], sc0_r[3][2], sc1_r[3][2];
#pragma unroll
    for (int q = 0; q < 3; q++) {
        swy_r[q][0] = swy[q * 64 + c0i]; swy_r[q][1] = swy[q * 64 + c0i + 1];
        sc0_r[q][0] = sc0[q * 64 + c0i]; sc0_r[q][1] = sc0[q * 64 + c0i + 1];
        sc1_r[q][0] = sc1[q * 64 + c0i]; sc1_r[q][1] = sc1[q * 64 + c0i + 1];
    }
    float bmu = b_mu[0], bsg = b_sigma[0];
    float wmu[2] = {W_mu[c0i], W_mu[c0i + 1]};
    float wsg[2] = {W_sigma[c0i], W_sigma[c0i + 1]};

    int gw = blockIdx.x * 8 + wid;
    const int wstride = gridDim.x * 8;

    float4 pf0, pf1;
    float pfy = 0.0f;
    if (gw < NWT) {
        const float4* src = (const float4*)X + (size_t)gw * 64;
        pf0 = src[tn];
        pf1 = src[tn + 32];
        if (tn < 8) pfy = Y[gw * 8 + tn];
    }

    for (int wt = gw; wt < NWT; wt += wstride) {
        __syncwarp();   // previous-iteration readers of buf/syw done
        {   // stage prefetched 8x32 X tile (transposed) + y
            int m = tn >> 3, kb = (tn & 7) * 4;
            buf[(kb + 0) * P1_BUF + m] = pf0.x;
            buf[(kb + 1) * P1_BUF + m] = pf0.y;
            buf[(kb + 2) * P1_BUF + m] = pf0.z;
            buf[(kb + 3) * P1_BUF + m] = pf0.w;
            int v = tn + 32;
            m = v >> 3; kb = (v & 7) * 4;
            buf[(kb + 0) * P1_BUF + m] = pf1.x;
            buf[(kb + 1) * P1_BUF + m] = pf1.y;
            buf[(kb + 2) * P1_BUF + m] = pf1.z;
            buf[(kb + 3) * P1_BUF + m] = pf1.w;
            if (tn < 8) syw[tn] = pfy;
        }
        __syncwarp();

        int nt = wt + wstride;
        if (nt < NWT) {   // next-tile loads hide behind both gemms
            const float4* src = (const float4*)X + (size_t)nt * 64;
            pf0 = src[tn];
            pf1 = src[tn + 32];
            if (tn < 8) pfy = Y[nt * 8 + tn];
        }

        float acc[8][3][2];
        gemm8<32>(buf, sW0, c0i, acc);    // layer0 x-part
        __syncwarp();                     // all lanes done reading X region

        float yv8[8];
#pragma unroll
        for (int i = 0; i < 8; i++) yv8[i] = syw[i];

        // layer0 epilogue -> h columns c0i, c0i+1 (k-slots for layer1)
#pragma unroll
        for (int j = 0; j < 2; j++) {
            float hv[8];
#pragma unroll
            for (int i = 0; i < 8; i++) {
                float gi = fmaf(yv8[i], swy_r[0][j], acc[i][0][j]) + sc0_r[0][j];
                float gg = fmaf(yv8[i], swy_r[1][j], acc[i][1][j]) + sc0_r[1][j];
                float go = fmaf(yv8[i], swy_r[2][j], acc[i][2][j]) + sc0_r[2][j];
                hv[i] = lstm_h(gi, gg, go);
            }
            float* hrow = buf + (c0i + j) * P1_BUF;
            *(float4*)hrow = make_float4(hv[0], hv[1], hv[2], hv[3]);
            *(float4*)(hrow + 4) = make_float4(hv[4], hv[5], hv[6], hv[7]);
        }
        __syncwarp();

        gemm8<64>(buf, sW1, c0i, acc);    // layer1

        float pmu[8], psg[8];
#pragma unroll
        for (int i = 0; i < 8; i++) {
            float smu = 0.0f, ssg = 0.0f;
#pragma unroll
            for (int j = 0; j < 2; j++) {
                float gi = acc[i][0][j] + sc1_r[0][j];
                float gg = acc[i][1][j] + sc1_r[1][j];
                float go = acc[i][2][j] + sc1_r[2][j];
                float h = fmaxf(lstm_h(gi, gg, go), 0.0f);
                smu = fmaf(h, wmu[j], smu);
                ssg = fmaf(h, wsg[j], ssg);
            }
            pmu[i] = smu; psg[i] = ssg;
        }
        reduce_mu_sig8(pmu, psg);
        if (tn == 0) {
            int r0 = wt * 8;
#pragma unroll
            for (int i = 0; i < 8; i++) {
                int r = r0 + i;
                int n = r / SL;
                int t = r - n * SL;
                float mu = pmu[i] + bmu;
                float sg = softplus_f(psg[i] + bsg) + 1e-6f;
                out_mu[n * TT + t] = mu;
                out_sig[n * TT + t] = sg;
                if (t == SL - 1) {
                    float d = yv8[i] - mu;
                    float lik = rsqrtf(6.283185307179586f * sg * sg) *
                                __expf(-d * d / (2.0f * sg * sg));
                    out_ypred[n * HZ] = lik;
                    g_carry[n] = lik;
                }
            }
        }
    }
}

// ---------------- phase 2: ALL 24 autoregressive steps, one kernel -----------
// 128 blocks x 32 series, 512 threads (16 warps x 2 rows) for latency hiding.
// Warp-private rows: only __syncwarp between steps. XGf prefetched one step
// ahead (independent of the carry) so its latency hides behind the gemm.
#define HST 34                     // H tile stride (floats, even for ull loads)
#define SM2_FLOATS (64 * GE + 64 * HST + 32 + GE + GE)
#define SM2_BYTES (SM2_FLOATS * 4)

__global__ __launch_bounds__(512, 1) void phase2_kernel(
    const float* __restrict__ W_mu, const float* __restrict__ b_mu,
    const float* __restrict__ W_sigma, const float* __restrict__ b_sigma,
    float* __restrict__ out_ypred, float* __restrict__ out_mu,
    float* __restrict__ out_sig) {
    extern __shared__ float sm[];
    float* sW1 = sm;                       // 12288
    float* sH  = sm + 64 * GE;             // 2176
    float* sy  = sH + 64 * HST;            // 32
    float* swy = sy + 32;                  // 192
    float* sc1 = swy + GE;                 // 192

    int tid = threadIdx.x, tn = tid & 31, tm = tid >> 5;
    int n0 = blockIdx.x * 32;
    {
        float4* d = (float4*)sW1; const float4* s = (const float4*)g_W1T;
        for (int i = tid; i < 3072; i += 512) d[i] = s[i];
    }
    if (tid < GE) { swy[tid] = g_Wy[tid]; sc1[tid] = g_C1[tid]; }
    if (tid < 32) sy[tid] = g_carry[n0 + tid];
    __syncthreads();

    int m0 = tm * 2, c0i = 2 * tn;
    float swy_r[3][2], sc1_r[3][2];
#pragma unroll
    for (int q = 0; q < 3; q++) {
        swy_r[q][0] = swy[q * 64 + c0i]; swy_r[q][1] = swy[q * 64 + c0i + 1];
        sc1_r[q][0] = sc1[q * 64 + c0i]; sc1_r[q][1] = sc1[q * 64 + c0i + 1];
    }
    float bmu = b_mu[0], bsg = b_sigma[0];
    float wmu[2] = {W_mu[c0i], W_mu[c0i + 1]};
    float wsg[2] = {W_sigma[c0i], W_sigma[c0i + 1]};

    // prefetch XGf for ht=0
    float2 cxi[2], cxg[2], cxo[2];
#pragma unroll
    for (int i = 0; i < 2; i++) {
        const float* xg = g_XGf + ((size_t)(n0 + m0 + i) * HZ) * GE;
        cxi[i] = *(const float2*)&xg[c0i];
        cxg[i] = *(const float2*)&xg[64 + c0i];
        cxo[i] = *(const float2*)&xg[128 + c0i];
    }

    for (int ht = 0; ht < HZ; ht++) {
        float yv[2];
        yv[0] = sy[m0];
        yv[1] = sy[m0 + 1];

        // layer0: prefetched XGf + rank-1 ynext term
#pragma unroll
        for (int j = 0; j < 2; j++) {
            float h0, h1;
            {
                float xi = j ? cxi[0].y : cxi[0].x;
                float xg = j ? cxg[0].y : cxg[0].x;
                float xo = j ? cxo[0].y : cxo[0].x;
                h0 = lstm_h(fmaf(yv[0], swy_r[0][j], xi),
                            fmaf(yv[0], swy_r[1][j], xg),
                            fmaf(yv[0], swy_r[2][j], xo));
            }
            {
                float xi = j ? cxi[1].y : cxi[1].x;
                float xg = j ? cxg[1].y : cxg[1].x;
                float xo = j ? cxo[1].y : cxo[1].x;
                h1 = lstm_h(fmaf(yv[1], swy_r[0][j], xi),
                            fmaf(yv[1], swy_r[1][j], xg),
                            fmaf(yv[1], swy_r[2][j], xo));
            }
            *(float2*)&sH[(c0i + j) * HST + m0] = make_float2(h0, h1);
        }
        __syncwarp();

        if (ht + 1 < HZ) {   // prefetch next step's XGf (carry-independent)
#pragma unroll
            for (int i = 0; i < 2; i++) {
                const float* xg =
                    g_XGf + ((size_t)(n0 + m0 + i) * HZ + ht + 1) * GE;
                cxi[i] = *(const float2*)&xg[c0i];
                cxg[i] = *(const float2*)&xg[64 + c0i];
                cxo[i] = *(const float2*)&xg[128 + c0i];
            }
        }

        // layer1 gemm: 2 rows x 6 cols per thread, packed row pair
        ull accp[3][2];
#pragma unroll
        for (int q = 0; q < 3; q++) { accp[q][0] = 0ULL; accp[q][1] = 0ULL; }
#pragma unroll 4
        for (int k = 0; k < 64; k++) {
            ull a0 = *(const ull*)(sH + k * HST + m0);
            ull bs[3][2];
#pragma unroll
            for (int q = 0; q < 3; q++) {
                float2 t = *(const float2*)&sW1[k * GE + q * 64 + c0i];
                bs[q][0] = splat2(t.x);
                bs[q][1] = splat2(t.y);
            }
#pragma unroll
            for (int q = 0; q < 3; q++) {
                ffma2(accp[q][0], a0, bs[q][0]);
                ffma2(accp[q][1], a0, bs[q][1]);
            }
        }
        float acc[2][3][2];
#pragma unroll
        for (int q = 0; q < 3; q++)
#pragma unroll
            for (int j = 0; j < 2; j++)
                unpack2(acc[0][q][j], acc[1][q][j], accp[q][j]);

        // layer1 epilogue + relu + mu/sigma dots
        float pmu[2], psg[2];
#pragma unroll
        for (int i = 0; i < 2; i++) {
            float smu = 0.0f, ssg = 0.0f;
#pragma unroll
            for (int j = 0; j < 2; j++) {
                float gi = acc[i][0][j] + sc1_r[0][j];
                float gg = acc[i][1][j] + sc1_r[1][j];
                float go = acc[i][2][j] + sc1_r[2][j];
                float h = fmaxf(lstm_h(gi, gg, go), 0.0f);
                smu = fmaf(h, wmu[j], smu);
                ssg = fmaf(h, wsg[j], ssg);
            }
            pmu[i] = smu; psg[i] = ssg;
        }
        reduce_mu_sig2(pmu, psg);
        __syncwarp();   // all lanes done reading sy for this step
        if (tn == 0) {
            int t = SL + ht;
#pragma unroll
            for (int i = 0; i < 2; i++) {
                int n = n0 + m0 + i;
                float mu = pmu[i] + bmu;
                float sg = softplus_f(psg[i] + bsg) + 1e-6f;
                out_mu[n * TT + t] = mu;
                out_sig[n * TT + t] = sg;
                float d = yv[i] - mu;   // ynext == carry in horizon region
                float lik = rsqrtf(6.283185307179586f * sg * sg) *
                            __expf(-d * d / (2.0f * sg * sg));
                sy[m0 + i] = lik;
                if (ht <= HZ - 2) out_ypred[n * HZ + ht + 1] = lik;
            }
        }
        __syncwarp();   // sy updates visible before next step's reads
    }
}

// ---------------- launcher ---------------------------------------------------
extern "C" void kernel_launch(void* const* d_in, const int* in_sizes, int n_in,
                              void* d_out, int out_size) {
    (void)in_sizes; (void)n_in; (void)out_size;
    const float* X       = (const float*)d_in[0];
    const float* Y       = (const float*)d_in[1];
    const float* Xf      = (const float*)d_in[2];
    const float* W_embed = (const float*)d_in[3];
    const float* b_embed = (const float*)d_in[4];
    const float* W_ih    = (const float*)d_in[5];
    const float* b_ih    = (const float*)d_in[6];
    const float* b_hh    = (const float*)d_in[7];
    const float* W_mu    = (const float*)d_in[8];
    const float* b_mu    = (const float*)d_in[9];
    const float* W_sigma = (const float*)d_in[10];
    const float* b_sigma = (const float*)d_in[11];

    float* out   = (float*)d_out;
    float* ypred = out;                 // (NS, HZ)
    float* omu   = out + NS * HZ;       // (NS, TT)
    float* osig  = omu + NS * TT;       // (NS, TT)

    cudaFuncSetAttribute(phase1_kernel,
                         cudaFuncAttributeMaxDynamicSharedMemorySize, SM1_BYTES);
    cudaFuncSetAttribute(phase2_kernel,
                         cudaFuncAttributeMaxDynamicSharedMemorySize, SM2_BYTES);

    setup_kernel<<<1, 256>>>(W_embed, b_embed, W_ih, b_ih, b_hh);
    xg_kernel<<<(NS * HZ) / 64, 256>>>(Xf);
    phase1_kernel<<<296, 256, SM1_BYTES>>>(X, Y, W_mu, b_mu, W_sigma, b_sigma,
                                           ypred, omu, osig);
    phase2_kernel<<<NS / 32, 512, SM2_BYTES>>>(W_mu, b_mu, W_sigma, b_sigma,
                                               ypred, omu, osig);
}